// round 7
// baseline (speedup 1.0000x reference)
#include <cuda_runtime.h>
#include <cstdint>
#include <cstddef>

#define B   32
#define T   2048
#define E   512
#define H   512
#define G4  2048
#define NCTA 128
#define THREADS 512
#define HS_STRIDE  516   // floats per row (512 + 4 pad)
#define HS_STRIDE4 129   // float4 per row

// ---- device scratch ----
__device__ float g_xg[(size_t)B * T * G4];     // precomputed x@Wx + bx + bh
__device__ float g_hbuf[2][2][16 * H];         // [team][parity][16 x 512]
__device__ unsigned g_bar[2];                  // per-team arrival counters

__device__ __forceinline__ void barn(int id, int cnt) {
    asm volatile("bar.sync %0, %1;" :: "r"(id), "r"(cnt) : "memory");
}
__device__ __forceinline__ unsigned ld_acq(const unsigned* p) {
    unsigned v;
    asm volatile("ld.acquire.gpu.global.u32 %0, [%1];" : "=r"(v) : "l"(p));
    return v;
}
__device__ __forceinline__ void red_release_add(unsigned* p, unsigned v) {
    asm volatile("red.release.gpu.global.add.u32 [%0], %1;" :: "l"(p), "r"(v)
                 : "memory");
}
__device__ __forceinline__ float sigm(float x) {
    return 1.f / (1.f + __expf(-x));
}
__device__ __forceinline__ float tanh_fast(float x) {
    return 2.f / (1.f + __expf(-2.f * x)) - 1.f;
}

__global__ void reset_bar_kernel() { g_bar[0] = 0; g_bar[1] = 0; }

// =====================================================================
// Kernel 1: xg = X@Wx + bx + bh (known-good: ~3.4 ms, fma-pipe bound)
// =====================================================================
__global__ __launch_bounds__(256) void xg_gemm_kernel(
    const float* __restrict__ X, const float* __restrict__ Wx,
    const float* __restrict__ bx, const float* __restrict__ bh)
{
    __shared__ float As[8][128];
    __shared__ float Bs[8][132];
    const int tid = threadIdx.x;
    const int mBase = blockIdx.y * 128;
    const int nBase = blockIdx.x * 128;
    const int arow = tid >> 1, acol = (tid & 1) * 4;
    const int brow = tid >> 5, bcol = (tid & 31) * 4;
    const int tm = (tid >> 4) * 8;
    const int tn = (tid & 15) * 8;

    float acc[8][8];
    #pragma unroll
    for (int i = 0; i < 8; i++)
        #pragma unroll
        for (int j = 0; j < 8; j++) acc[i][j] = 0.f;

    const float* Aptr = X  + (size_t)(mBase + arow) * E + acol;
    const float* Bptr = Wx + (size_t)brow * G4 + nBase + bcol;

    for (int k0 = 0; k0 < E; k0 += 8) {
        float4 av = *(const float4*)(Aptr + k0);
        float4 bv = *(const float4*)(Bptr + (size_t)k0 * G4);
        __syncthreads();
        As[acol + 0][arow] = av.x;
        As[acol + 1][arow] = av.y;
        As[acol + 2][arow] = av.z;
        As[acol + 3][arow] = av.w;
        *(float4*)&Bs[brow][bcol] = bv;
        __syncthreads();
        #pragma unroll
        for (int k = 0; k < 8; k++) {
            float a[8], b[8];
            *(float4*)(a)     = *(const float4*)&As[k][tm];
            *(float4*)(a + 4) = *(const float4*)&As[k][tm + 4];
            *(float4*)(b)     = *(const float4*)&Bs[k][tn];
            *(float4*)(b + 4) = *(const float4*)&Bs[k][tn + 4];
            #pragma unroll
            for (int i = 0; i < 8; i++)
                #pragma unroll
                for (int j = 0; j < 8; j++)
                    acc[i][j] = fmaf(a[i], b[j], acc[i][j]);
        }
    }

    float bsum[8];
    #pragma unroll
    for (int j = 0; j < 8; j++)
        bsum[j] = bx[nBase + tn + j] + bh[nBase + tn + j];

    #pragma unroll
    for (int i = 0; i < 8; i++) {
        size_t row = (size_t)(mBase + tm + i);
        float4 v0 = make_float4(acc[i][0] + bsum[0], acc[i][1] + bsum[1],
                                acc[i][2] + bsum[2], acc[i][3] + bsum[3]);
        float4 v1 = make_float4(acc[i][4] + bsum[4], acc[i][5] + bsum[5],
                                acc[i][6] + bsum[6], acc[i][7] + bsum[7]);
        *(float4*)&g_xg[row * G4 + nBase + tn]     = v0;
        *(float4*)&g_xg[row * G4 + nBase + tn + 4] = v1;
    }
}

// =====================================================================
// Kernel 2: persistent recurrence, two SMT teams + PER-WARP SLICE RELOAD.
// Team = 8 warps, 16 batches. Warp w consumes only h[k in [w*64,w*64+64)],
// so each warp polls the team counter itself, reloads only its own 16x16
// float4 slice into its private smem column stripe (no team barriers
// around the reload), then runs the mainloop. Only two barriers per step:
// barT (partials -> epilogue) and barR (h stores -> release arrival).
// Arrival: red.release.gpu.add (no full GPU membar).
// =====================================================================
__global__ __launch_bounds__(THREADS, 1) void lstm_rec_kernel(
    const float* __restrict__ Wh, float* __restrict__ out)
{
    extern __shared__ float sm[];
    float* whs = sm;                                // 16 x 516 (shared)

    const int tid   = threadIdx.x;
    const int team  = tid >> 8;        // 0 or 1
    const int tt    = tid & 255;       // tid within team
    const int lane  = tid & 31;
    const int wteam = tt >> 5;         // warp index in team, 0..7
    const int cta   = blockIdx.x;

    float*  hslot = sm + (16 + team * 16) * HS_STRIDE;
    float4* redt  = (float4*)(sm + 48 * HS_STRIDE) + team * 512;

    // Wh slice: whs[c][k] = Wh[k][(c>>2)*512 + cta*4 + (c&3)]
    for (int idx = tid; idx < 16 * 512; idx += THREADS) {
        int c = idx >> 9;
        int k = idx & 511;
        int col = ((c >> 2) << 9) + cta * 4 + (c & 3);
        whs[c * HS_STRIDE + k] = Wh[(size_t)k * G4 + col];
    }
    for (int idx = tid; idx < 32 * HS_STRIDE; idx += THREADS)
        sm[16 * HS_STRIDE + idx] = 0.f;
    __syncthreads();   // teams independent after this

    const int lb = lane & 7;           // batch-in-team = lb + 8j
    const int lc = lane >> 3;          // local hidden 0..3
    const float4* whs4 = (const float4*)whs;
    const float4* hs4  = (const float4*)hslot;
    float4*       hs4w = (float4*)hslot;

    // reducer identity (tt < 64): (batch bl, local hidden hl)
    const int bl    = tt >> 2;                 // 0..15
    const int hl    = tt & 3;                  // 0..3
    const int hid   = cta * 4 + hl;            // global hidden index
    const int bglob = team * 16 + bl;          // global batch
    float c_state = 0.f;

    const int barT = 1 + team;   // team-wide barrier (256 threads)
    const int barR = 3 + team;   // reducer barrier (64 threads)

    for (int t = 0; t < T; t++) {
        // xg prefetch — hoisted above the poll to hide DRAM latency
        float xp0 = 0.f, xp1 = 0.f, xp2 = 0.f, xp3 = 0.f;
        if (tt < 64) {
            const float* xr = g_xg + ((size_t)bglob * T + t) * G4 + hid;
            xp0 = __ldcs(xr);
            xp1 = __ldcs(xr + 512);
            xp2 = __ldcs(xr + 1024);
            xp3 = __ldcs(xr + 1536);
        }

        if (t > 0) {
            // per-warp poll: wait for all CTAs' step-(t-1) publication
            if (lane == 0) {
                unsigned target = 128u * (unsigned)t;
                int spins = 0;
                while (ld_acq(&g_bar[team]) < target) {
                    if (++spins > 64) { __nanosleep(64); }
                }
            }
            __syncwarp();
            // per-warp slice reload: rows 0..15, cols [wteam*16, +16) float4
            const float4* src = (const float4*)g_hbuf[team][(t - 1) & 1];
            const int cb = wteam * 16;
            #pragma unroll
            for (int q = 0; q < 8; q++) {
                int idx = lane + 32 * q;       // 0..255
                int b   = idx >> 4;
                int kk  = idx & 15;
                hs4w[b * HS_STRIDE4 + cb + kk] =
                    __ldcg(src + b * 128 + cb + kk);
            }
            __syncwarp();
        }

        // ---- mainloop: k-slice [wteam*64, +64), 2b x 4gate lane tile ----
        float acc[2][4];
        #pragma unroll
        for (int j = 0; j < 2; j++)
            #pragma unroll
            for (int i = 0; i < 4; i++) acc[j][i] = 0.f;

        const int kb = wteam * 16;
        #pragma unroll 4
        for (int q = 0; q < 16; q++) {
            const int kv = kb + q;
            float4 wv[4];
            #pragma unroll
            for (int i = 0; i < 4; i++)
                wv[i] = whs4[(lc + 4 * i) * HS_STRIDE4 + kv];
            #pragma unroll
            for (int j = 0; j < 2; j++) {
                float4 hh = hs4[(lb + 8 * j) * HS_STRIDE4 + kv];
                #pragma unroll
                for (int i = 0; i < 4; i++) {
                    acc[j][i] = fmaf(hh.x, wv[i].x, acc[j][i]);
                    acc[j][i] = fmaf(hh.y, wv[i].y, acc[j][i]);
                    acc[j][i] = fmaf(hh.z, wv[i].z, acc[j][i]);
                    acc[j][i] = fmaf(hh.w, wv[i].w, acc[j][i]);
                }
            }
        }

        // partials: redt[w*64 + b*4 + hl]
        #pragma unroll
        for (int j = 0; j < 2; j++)
            redt[wteam * 64 + (lb + 8 * j) * 4 + lc] =
                make_float4(acc[j][0], acc[j][1], acc[j][2], acc[j][3]);
        barn(barT, 256);

        // ---- epilogue: 64 reducers, each owns (bl, hid) ----
        if (tt < 64) {
            float4 s = make_float4(0.f, 0.f, 0.f, 0.f);
            #pragma unroll
            for (int w = 0; w < 8; w++) {
                float4 v = redt[w * 64 + tt];
                s.x += v.x; s.y += v.y; s.z += v.z; s.w += v.w;
            }
            float f  = sigm(s.x + xp0);
            float ig = sigm(s.y + xp1);
            float cc = tanh_fast(s.z + xp2);
            float og = sigm(s.w + xp3);
            c_state = f * c_state + ig * cc;
            float h_new = og * tanh_fast(c_state);
            g_hbuf[team][t & 1][bl * H + hid] = h_new;
            if (t == T - 1) {
                out[bglob * H + hid]         = h_new;
                out[B * H + bglob * H + hid] = c_state;
            }
            barn(barR, 64);                    // order all 64 h stores
            if (tt == 0) red_release_add(&g_bar[team], 1u);
        }
        // non-reducer warps run ahead to the next step's poll
    }
}

// =====================================================================
extern "C" void kernel_launch(void* const* d_in, const int* in_sizes, int n_in,
                              void* d_out, int out_size)
{
    const float* x  = (const float*)d_in[0];
    const float* Wx = (const float*)d_in[1];
    const float* Wh = (const float*)d_in[2];
    const float* bx = (const float*)d_in[3];
    const float* bh = (const float*)d_in[4];
    float* out = (float*)d_out;

    reset_bar_kernel<<<1, 1>>>();

    dim3 g1(G4 / 128, (B * T) / 128);
    xg_gemm_kernel<<<g1, 256>>>(x, Wx, bx, bh);

    const int smem_bytes =
        (48 * HS_STRIDE + 2 * 512 * 4) * (int)sizeof(float);
    cudaFuncSetAttribute(lstm_rec_kernel,
                         cudaFuncAttributeMaxDynamicSharedMemorySize, smem_bytes);
    lstm_rec_kernel<<<NCTA, THREADS, smem_bytes>>>(Wh, out);
}

// round 8
// speedup vs baseline: 1.6657x; 1.6657x over previous
#include <cuda_runtime.h>
#include <cstdint>
#include <cstddef>

#define B   32
#define T   2048
#define E   512
#define H   512
#define G4  2048
#define NCTA 128
#define THREADS 512
#define HS_STRIDE  516   // floats per row (512 + 4 pad)
#define HS_STRIDE4 129   // float4 per row

// ---- device scratch ----
__device__ float g_xg[(size_t)B * T * G4];     // precomputed x@Wx + bx + bh
__device__ float g_hbuf[2][2][16 * H];         // [team][parity][16 x 512]
__device__ unsigned g_bar[2];                  // per-team arrival counters

__device__ __forceinline__ void barn(int id, int cnt) {
    asm volatile("bar.sync %0, %1;" :: "r"(id), "r"(cnt) : "memory");
}
__device__ __forceinline__ unsigned ld_acq(const unsigned* p) {
    unsigned v;
    asm volatile("ld.acquire.gpu.global.u32 %0, [%1];" : "=r"(v) : "l"(p));
    return v;
}
__device__ __forceinline__ void red_release_add(unsigned* p, unsigned v) {
    asm volatile("red.release.gpu.global.add.u32 [%0], %1;" :: "l"(p), "r"(v)
                 : "memory");
}
__device__ __forceinline__ float sigm(float x) {
    return 1.f / (1.f + __expf(-x));
}
__device__ __forceinline__ float tanh_fast(float x) {
    return 2.f / (1.f + __expf(-2.f * x)) - 1.f;
}

// =====================================================================
// Kernel 1: xg = X@Wx + bx + bh (~3.4 ms, fma-pipe bound).
// Block (0,0) also resets the lstm barrier counters (runs before lstm
// in stream order; no extra launch, keeps ncu slots on real kernels).
// =====================================================================
__global__ __launch_bounds__(256) void xg_gemm_kernel(
    const float* __restrict__ X, const float* __restrict__ Wx,
    const float* __restrict__ bx, const float* __restrict__ bh)
{
    if (blockIdx.x == 0 && blockIdx.y == 0 && threadIdx.x == 0) {
        g_bar[0] = 0;
        g_bar[1] = 0;
    }

    __shared__ float As[8][128];
    __shared__ float Bs[8][132];
    const int tid = threadIdx.x;
    const int mBase = blockIdx.y * 128;
    const int nBase = blockIdx.x * 128;
    const int arow = tid >> 1, acol = (tid & 1) * 4;
    const int brow = tid >> 5, bcol = (tid & 31) * 4;
    const int tm = (tid >> 4) * 8;
    const int tn = (tid & 15) * 8;

    float acc[8][8];
    #pragma unroll
    for (int i = 0; i < 8; i++)
        #pragma unroll
        for (int j = 0; j < 8; j++) acc[i][j] = 0.f;

    const float* Aptr = X  + (size_t)(mBase + arow) * E + acol;
    const float* Bptr = Wx + (size_t)brow * G4 + nBase + bcol;

    for (int k0 = 0; k0 < E; k0 += 8) {
        float4 av = *(const float4*)(Aptr + k0);
        float4 bv = *(const float4*)(Bptr + (size_t)k0 * G4);
        __syncthreads();
        As[acol + 0][arow] = av.x;
        As[acol + 1][arow] = av.y;
        As[acol + 2][arow] = av.z;
        As[acol + 3][arow] = av.w;
        *(float4*)&Bs[brow][bcol] = bv;
        __syncthreads();
        #pragma unroll
        for (int k = 0; k < 8; k++) {
            float a[8], b[8];
            *(float4*)(a)     = *(const float4*)&As[k][tm];
            *(float4*)(a + 4) = *(const float4*)&As[k][tm + 4];
            *(float4*)(b)     = *(const float4*)&Bs[k][tn];
            *(float4*)(b + 4) = *(const float4*)&Bs[k][tn + 4];
            #pragma unroll
            for (int i = 0; i < 8; i++)
                #pragma unroll
                for (int j = 0; j < 8; j++)
                    acc[i][j] = fmaf(a[i], b[j], acc[i][j]);
        }
    }

    float bsum[8];
    #pragma unroll
    for (int j = 0; j < 8; j++)
        bsum[j] = bx[nBase + tn + j] + bh[nBase + tn + j];

    #pragma unroll
    for (int i = 0; i < 8; i++) {
        size_t row = (size_t)(mBase + tm + i);
        float4 v0 = make_float4(acc[i][0] + bsum[0], acc[i][1] + bsum[1],
                                acc[i][2] + bsum[2], acc[i][3] + bsum[3]);
        float4 v1 = make_float4(acc[i][4] + bsum[4], acc[i][5] + bsum[5],
                                acc[i][6] + bsum[6], acc[i][7] + bsum[7]);
        *(float4*)&g_xg[row * G4 + nBase + tn]     = v0;
        *(float4*)&g_xg[row * G4 + nBase + tn + 4] = v1;
    }
}

// =====================================================================
// Kernel 2: persistent recurrence, TWO SMT TEAMS (round-6 structure).
// Exactly one poller per team per CTA (256 chip-wide pollers — keeps the
// counter word uncontended; the round-7 per-warp polling regression is
// documented). Arrival uses red.release (barR orders the h stores).
// =====================================================================
__global__ __launch_bounds__(THREADS, 1) void lstm_rec_kernel(
    const float* __restrict__ Wh, float* __restrict__ out)
{
    extern __shared__ float sm[];
    float* whs = sm;                                // 16 x 516 (shared)

    const int tid   = threadIdx.x;
    const int team  = tid >> 8;        // 0 or 1
    const int tt    = tid & 255;       // tid within team
    const int lane  = tid & 31;
    const int wteam = tt >> 5;         // warp index in team, 0..7
    const int cta   = blockIdx.x;

    float*  hslot = sm + (16 + team * 16) * HS_STRIDE;
    float4* redt  = (float4*)(sm + 48 * HS_STRIDE) + team * 512;

    // Wh slice: whs[c][k] = Wh[k][(c>>2)*512 + cta*4 + (c&3)]
    for (int idx = tid; idx < 16 * 512; idx += THREADS) {
        int c = idx >> 9;
        int k = idx & 511;
        int col = ((c >> 2) << 9) + cta * 4 + (c & 3);
        whs[c * HS_STRIDE + k] = Wh[(size_t)k * G4 + col];
    }
    for (int idx = tid; idx < 32 * HS_STRIDE; idx += THREADS)
        sm[16 * HS_STRIDE + idx] = 0.f;
    __syncthreads();   // teams independent after this

    const int lb = lane & 7;           // batch-in-team = lb + 8j
    const int lc = lane >> 3;          // local hidden 0..3
    const float4* whs4 = (const float4*)whs;
    const float4* hs4  = (const float4*)hslot;
    float4*       hs4w = (float4*)hslot;

    // reducer identity (tt < 64): (batch bl, local hidden hl)
    const int bl    = tt >> 2;                 // 0..15
    const int hl    = tt & 3;                  // 0..3
    const int hid   = cta * 4 + hl;            // global hidden index
    const int bglob = team * 16 + bl;          // global batch
    float c_state = 0.f;

    const int barT = 1 + team;   // team-wide barrier (256 threads)
    const int barR = 3 + team;   // reducer barrier (64 threads)

    for (int t = 0; t < T; t++) {
        // xg prefetch — hoisted above the poll to hide DRAM latency
        float xp0 = 0.f, xp1 = 0.f, xp2 = 0.f, xp3 = 0.f;
        if (tt < 64) {
            const float* xr = g_xg + ((size_t)bglob * T + t) * G4 + hid;
            xp0 = __ldcs(xr);
            xp1 = __ldcs(xr + 512);
            xp2 = __ldcs(xr + 1024);
            xp3 = __ldcs(xr + 1536);
        }

        if (t > 0) {
            // single poller per team: wait for step-(t-1) publication
            if (tt == 0) {
                unsigned target = 128u * (unsigned)t;
                int spins = 0;
                while (ld_acq(&g_bar[team]) < target) {
                    if (++spins > 64) { __nanosleep(64); }
                }
            }
            barn(barT, 256);
            // reload team h(t-1): 2048 float4 over 256 threads
            const float4* src = (const float4*)g_hbuf[team][(t - 1) & 1];
            #pragma unroll
            for (int q = 0; q < 8; q++) {
                int v  = tt + 256 * q;
                int b  = v >> 7;
                int kk = v & 127;
                hs4w[b * HS_STRIDE4 + kk] = __ldcg(src + v);
            }
            barn(barT, 256);
        }

        // ---- mainloop: k-slice [wteam*64, +64), 2b x 4gate lane tile ----
        float acc[2][4];
        #pragma unroll
        for (int j = 0; j < 2; j++)
            #pragma unroll
            for (int i = 0; i < 4; i++) acc[j][i] = 0.f;

        const int kb = wteam * 16;
        #pragma unroll 4
        for (int q = 0; q < 16; q++) {
            const int kv = kb + q;
            float4 wv[4];
            #pragma unroll
            for (int i = 0; i < 4; i++)
                wv[i] = whs4[(lc + 4 * i) * HS_STRIDE4 + kv];
            #pragma unroll
            for (int j = 0; j < 2; j++) {
                float4 hh = hs4[(lb + 8 * j) * HS_STRIDE4 + kv];
                #pragma unroll
                for (int i = 0; i < 4; i++) {
                    acc[j][i] = fmaf(hh.x, wv[i].x, acc[j][i]);
                    acc[j][i] = fmaf(hh.y, wv[i].y, acc[j][i]);
                    acc[j][i] = fmaf(hh.z, wv[i].z, acc[j][i]);
                    acc[j][i] = fmaf(hh.w, wv[i].w, acc[j][i]);
                }
            }
        }

        // partials: redt[w*64 + b*4 + hl]
        #pragma unroll
        for (int j = 0; j < 2; j++)
            redt[wteam * 64 + (lb + 8 * j) * 4 + lc] =
                make_float4(acc[j][0], acc[j][1], acc[j][2], acc[j][3]);
        barn(barT, 256);

        // ---- epilogue: 64 reducers, each owns (bl, hid) ----
        if (tt < 64) {
            float4 s = make_float4(0.f, 0.f, 0.f, 0.f);
            #pragma unroll
            for (int w = 0; w < 8; w++) {
                float4 v = redt[w * 64 + tt];
                s.x += v.x; s.y += v.y; s.z += v.z; s.w += v.w;
            }
            float f  = sigm(s.x + xp0);
            float ig = sigm(s.y + xp1);
            float cc = tanh_fast(s.z + xp2);
            float og = sigm(s.w + xp3);
            c_state = f * c_state + ig * cc;
            float h_new = og * tanh_fast(c_state);
            g_hbuf[team][t & 1][bl * H + hid] = h_new;
            if (t == T - 1) {
                out[bglob * H + hid]         = h_new;
                out[B * H + bglob * H + hid] = c_state;
            }
            barn(barR, 64);                    // order the 64 h stores
            if (tt == 0) red_release_add(&g_bar[team], 1u);
        }
        // non-reducer warps run ahead to the next step's poll barrier
    }
}

// =====================================================================
extern "C" void kernel_launch(void* const* d_in, const int* in_sizes, int n_in,
                              void* d_out, int out_size)
{
    const float* x  = (const float*)d_in[0];
    const float* Wx = (const float*)d_in[1];
    const float* Wh = (const float*)d_in[2];
    const float* bx = (const float*)d_in[3];
    const float* bh = (const float*)d_in[4];
    float* out = (float*)d_out;

    dim3 g1(G4 / 128, (B * T) / 128);
    xg_gemm_kernel<<<g1, 256>>>(x, Wx, bx, bh);

    const int smem_bytes =
        (48 * HS_STRIDE + 2 * 512 * 4) * (int)sizeof(float);
    cudaFuncSetAttribute(lstm_rec_kernel,
                         cudaFuncAttributeMaxDynamicSharedMemorySize, smem_bytes);
    lstm_rec_kernel<<<NCTA, THREADS, smem_bytes>>>(Wh, out);
}